// round 8
// baseline (speedup 1.0000x reference)
#include <cuda_runtime.h>
#include <cuda_bf16.h>
#include <cuda_fp16.h>
#include <cstdint>

// Problem constants (shapes are fixed by the dataset)
#define NN 50000
#define EE 800000
#define HC 256      // HEADS*OUT_C
#define HEADS 4

// Scratch (device globals -- no allocation allowed in kernel_launch)
__device__ __half g_hf[(size_t)NN * HC];          // h in fp16, 25.6 MB
__device__ __nv_bfloat16 g_wh[HC * HC];           // W hi bf16 [k][n]
__device__ __nv_bfloat16 g_wl[HC * HC];           // W lo bf16 [k][n]
__device__ float g_asrc[NN * HEADS];
__device__ float g_adst[NN * HEADS];
__device__ int   g_cnt[NN];
__device__ int   g_off[NN + 1];
__device__ int   g_cur[NN];
__device__ int   g_esrc[EE];
__device__ int   g_bsum[64];

__device__ __forceinline__ void split2(float x, float y,
                                       uint32_t& hi, uint32_t& lo) {
    __nv_bfloat16 hx = __float2bfloat16_rn(x);
    __nv_bfloat16 hy = __float2bfloat16_rn(y);
    __nv_bfloat16 lx = __float2bfloat16_rn(x - __bfloat162float(hx));
    __nv_bfloat16 ly = __float2bfloat16_rn(y - __bfloat162float(hy));
    hi = ((uint32_t)__bfloat16_as_ushort(hy) << 16) | __bfloat16_as_ushort(hx);
    lo = ((uint32_t)__bfloat16_as_ushort(ly) << 16) | __bfloat16_as_ushort(lx);
}

// ---------------------------------------------------------------------------
__global__ void zero_kernel(int n) {
    int i = blockIdx.x * blockDim.x + threadIdx.x;
    if (i < n) g_cnt[i] = 0;
    if (i < n * HEADS) { g_asrc[i] = 0.f; g_adst[i] = 0.f; }
}

// ---------------------------------------------------------------------------
// Preconvert W only (128 KB, reused by all 391 blocks).
__global__ __launch_bounds__(256) void convertW_kernel(
    const float* __restrict__ Wm, int nw8)
{
    int i = blockIdx.x * blockDim.x + threadIdx.x;
    if (i >= nw8) return;
    const float4* src = (const float4*)Wm + (size_t)i * 2;
    float4 v0 = src[0], v1 = src[1];
    uint4 hi, lo;
    split2(v0.x, v0.y, hi.x, lo.x);
    split2(v0.z, v0.w, hi.y, lo.y);
    split2(v1.x, v1.y, hi.z, lo.z);
    split2(v1.z, v1.w, hi.w, lo.w);
    ((uint4*)g_wh)[i] = hi;
    ((uint4*)g_wl)[i] = lo;
}

// ---------------------------------------------------------------------------
// Tensor-core GEMM: h[M,256] = X[M,256] * W[256,256], fp32-equivalent via
// 3-term bf16 split. X is read ONCE as fp32 and split in-kernel; W comes
// preconverted. ldmatrix fragment loads. Epilogue: fp16 h + fused att dots.
// Tile: BM=128, BN=256, BK=32. 8 warps (2x4), warp tile 64x64, mma m16n8k16.

#define BM 128
#define BN 256
#define BK 32
#define LDA 40    // A smem row stride (bf16): 80B = 5 chunks -> conflict-free
#define LDB 264   // B smem row stride (bf16): 528B = 33 chunks -> conflict-free
#define SMEM_AH 0
#define SMEM_AL (BM * LDA * 2)                    // 10240
#define SMEM_BH (2 * BM * LDA * 2)                // 20480
#define SMEM_BL (2 * BM * LDA * 2 + BK * LDB * 2) // 37376
#define SMEM_TOT (2 * BM * LDA * 2 + 2 * BK * LDB * 2)  // 54272

__device__ __forceinline__ void mma_bf16(float* c,
    uint32_t a0, uint32_t a1, uint32_t a2, uint32_t a3,
    uint32_t b0, uint32_t b1)
{
    asm volatile(
        "mma.sync.aligned.m16n8k16.row.col.f32.bf16.bf16.f32 "
        "{%0,%1,%2,%3}, {%4,%5,%6,%7}, {%8,%9}, {%0,%1,%2,%3};"
        : "+f"(c[0]), "+f"(c[1]), "+f"(c[2]), "+f"(c[3])
        : "r"(a0), "r"(a1), "r"(a2), "r"(a3), "r"(b0), "r"(b1));
}

__device__ __forceinline__ void ldsm_x4(uint32_t addr, uint32_t* r) {
    asm volatile(
        "ldmatrix.sync.aligned.m8n8.x4.shared.b16 {%0,%1,%2,%3}, [%4];"
        : "=r"(r[0]), "=r"(r[1]), "=r"(r[2]), "=r"(r[3]) : "r"(addr));
}

__device__ __forceinline__ void ldsm_x4_trans(uint32_t addr, uint32_t* r) {
    asm volatile(
        "ldmatrix.sync.aligned.m8n8.x4.trans.shared.b16 {%0,%1,%2,%3}, [%4];"
        : "=r"(r[0]), "=r"(r[1]), "=r"(r[2]), "=r"(r[3]) : "r"(addr));
}

__global__ __launch_bounds__(256, 1) void gemm_bf16x3_kernel(
    const float* __restrict__ X,
    const float* __restrict__ att_src, const float* __restrict__ att_dst,
    int M)
{
    extern __shared__ char smem_raw[];
    __nv_bfloat16* Ah = (__nv_bfloat16*)(smem_raw + SMEM_AH);   // [row][k]
    __nv_bfloat16* Al = (__nv_bfloat16*)(smem_raw + SMEM_AL);
    __nv_bfloat16* Bh = (__nv_bfloat16*)(smem_raw + SMEM_BH);   // [k][n]
    __nv_bfloat16* Bl = (__nv_bfloat16*)(smem_raw + SMEM_BL);

    const int tid  = threadIdx.x;
    const int warp = tid >> 5;
    const int lane = tid & 31;
    const int gid  = lane >> 2;    // row within 8
    const int tig  = lane & 3;     // thread in group
    const int bm = blockIdx.y * BM;
    const int wm = (warp >> 2) * 64;   // warp row base (2 rows of warps)
    const int wn = (warp & 3) * 64;    // warp col base (4 cols of warps)

    const uint32_t ah_base = (uint32_t)__cvta_generic_to_shared(Ah);
    const uint32_t al_base = (uint32_t)__cvta_generic_to_shared(Al);
    const uint32_t bh_base = (uint32_t)__cvta_generic_to_shared(Bh);
    const uint32_t bl_base = (uint32_t)__cvta_generic_to_shared(Bl);

    float acc[4][8][4];
#pragma unroll
    for (int mi = 0; mi < 4; mi++)
#pragma unroll
        for (int ni = 0; ni < 8; ni++)
#pragma unroll
            for (int r = 0; r < 4; r++) acc[mi][ni][r] = 0.f;

    // A loader: 2 threads/row, 16 fp32 each. B loader: 8 threads/k-row, 32 n.
    const int a_row = tid >> 1;
    const int a_c   = (tid & 1) * 16;
    const int b_k   = tid >> 3;
    const int b_n   = (tid & 7) * 32;
    const int a_grow = bm + a_row;

    for (int k0 = 0; k0 < 256; k0 += BK) {
        // --- A tile: load X fp32, split to bf16 hi/lo in-kernel ---
        {
            const float4* src =
                (const float4*)(X + (size_t)a_grow * 256 + k0 + a_c);
            int off = a_row * LDA + a_c;
#pragma unroll
            for (int i = 0; i < 4; i++) {
                float4 v = (a_grow < M) ? src[i]
                                        : make_float4(0.f, 0.f, 0.f, 0.f);
                uint32_t h0, l0, h1, l1;
                split2(v.x, v.y, h0, l0);
                split2(v.z, v.w, h1, l1);
                *(uint2*)&Ah[off + i * 4] = make_uint2(h0, h1);
                *(uint2*)&Al[off + i * 4] = make_uint2(l0, l1);
            }
        }
        // --- B tile: preconverted bf16, [k][n] coalesced both ways ---
        {
            const uint4* sh =
                (const uint4*)(g_wh + (size_t)(k0 + b_k) * 256 + b_n);
            const uint4* sl =
                (const uint4*)(g_wl + (size_t)(k0 + b_k) * 256 + b_n);
            int off = b_k * LDB + b_n;
#pragma unroll
            for (int i = 0; i < 4; i++) {
                *(uint4*)&Bh[off + i * 8] = sh[i];
                *(uint4*)&Bl[off + i * 8] = sl[i];
            }
        }
        __syncthreads();

#pragma unroll
        for (int kk = 0; kk < 2; kk++) {       // two k16 steps per BK
            const int c0 = kk * 16;
            uint32_t ah[4][4], al[4][4], bh[8][2], bl[8][2];
            const uint32_t a_off =
                ((uint32_t)(wm + (lane & 15)) * LDA + c0 + ((lane >> 4) << 3)) * 2;
#pragma unroll
            for (int mi = 0; mi < 4; mi++) {
                ldsm_x4(ah_base + a_off + mi * 16 * LDA * 2, ah[mi]);
                ldsm_x4(al_base + a_off + mi * 16 * LDA * 2, al[mi]);
            }
            const uint32_t b_off =
                ((uint32_t)(c0 + (lane & 15)) * LDB + wn + ((lane >> 4) << 3)) * 2;
#pragma unroll
            for (int nip = 0; nip < 4; nip++) {
                uint32_t t[4];
                ldsm_x4_trans(bh_base + b_off + nip * 16 * 2, t);
                bh[2*nip][0] = t[0]; bh[2*nip][1] = t[1];
                bh[2*nip+1][0] = t[2]; bh[2*nip+1][1] = t[3];
                ldsm_x4_trans(bl_base + b_off + nip * 16 * 2, t);
                bl[2*nip][0] = t[0]; bl[2*nip][1] = t[1];
                bl[2*nip+1][0] = t[2]; bl[2*nip+1][1] = t[3];
            }
#pragma unroll
            for (int mi = 0; mi < 4; mi++)
#pragma unroll
                for (int ni = 0; ni < 8; ni++) {
                    mma_bf16(acc[mi][ni], ah[mi][0], ah[mi][1], ah[mi][2],
                             ah[mi][3], bh[ni][0], bh[ni][1]);
                    mma_bf16(acc[mi][ni], ah[mi][0], ah[mi][1], ah[mi][2],
                             ah[mi][3], bl[ni][0], bl[ni][1]);
                    mma_bf16(acc[mi][ni], al[mi][0], al[mi][1], al[mi][2],
                             al[mi][3], bh[ni][0], bh[ni][1]);
                }
        }
        __syncthreads();
    }

    // --- epilogue: fp16 store of h + fused attention dot partials ---
    const int head = wn >> 6;    // each warp's 64 cols are exactly one head
#pragma unroll
    for (int mi = 0; mi < 4; mi++) {
        int r0 = bm + wm + mi * 16 + gid;
        int r1 = r0 + 8;
        float ps0 = 0.f, pd0 = 0.f, ps1 = 0.f, pd1 = 0.f;
#pragma unroll
        for (int ni = 0; ni < 8; ni++) {
            int col = wn + ni * 8 + tig * 2;
            float as0 = att_src[col], as1 = att_src[col + 1];
            float ad0 = att_dst[col], ad1 = att_dst[col + 1];
            ps0 += acc[mi][ni][0] * as0 + acc[mi][ni][1] * as1;
            pd0 += acc[mi][ni][0] * ad0 + acc[mi][ni][1] * ad1;
            ps1 += acc[mi][ni][2] * as0 + acc[mi][ni][3] * as1;
            pd1 += acc[mi][ni][2] * ad0 + acc[mi][ni][3] * ad1;
            if (r0 < M)
                *(__half2*)(g_hf + (size_t)r0 * 256 + col) =
                    __floats2half2_rn(acc[mi][ni][0], acc[mi][ni][1]);
            if (r1 < M)
                *(__half2*)(g_hf + (size_t)r1 * 256 + col) =
                    __floats2half2_rn(acc[mi][ni][2], acc[mi][ni][3]);
        }
        // reduce across the 4 tig lanes (same output row) -> 1 atomic per row
        ps0 += __shfl_xor_sync(0xffffffffu, ps0, 1);
        ps0 += __shfl_xor_sync(0xffffffffu, ps0, 2);
        pd0 += __shfl_xor_sync(0xffffffffu, pd0, 1);
        pd0 += __shfl_xor_sync(0xffffffffu, pd0, 2);
        ps1 += __shfl_xor_sync(0xffffffffu, ps1, 1);
        ps1 += __shfl_xor_sync(0xffffffffu, ps1, 2);
        pd1 += __shfl_xor_sync(0xffffffffu, pd1, 1);
        pd1 += __shfl_xor_sync(0xffffffffu, pd1, 2);
        if (tig == 0) {
            if (r0 < M) {
                atomicAdd(&g_asrc[r0 * HEADS + head], ps0);
                atomicAdd(&g_adst[r0 * HEADS + head], pd0);
            }
            if (r1 < M) {
                atomicAdd(&g_asrc[r1 * HEADS + head], ps1);
                atomicAdd(&g_adst[r1 * HEADS + head], pd1);
            }
        }
    }
}

// ---------------------------------------------------------------------------
// edge_index arrives as int32 (JAX x64 disabled -> int64 randint is int32).
__global__ void hist_kernel(const int* __restrict__ ei, int E) {
    int i = blockIdx.x * blockDim.x + threadIdx.x;
    if (i < E) {
        int d = ei[E + i];
        atomicAdd(&g_cnt[d], 1);
    }
}

// ---------------------------------------------------------------------------
// Parallel scan: per-block scan -> block-sums scan -> carry add.
__global__ __launch_bounds__(1024) void scan1_kernel(int n) {
    __shared__ int sd[1024];
    int i = blockIdx.x * 1024 + threadIdx.x;
    int v = (i < n) ? g_cnt[i] : 0;
    sd[threadIdx.x] = v;
    __syncthreads();
#pragma unroll
    for (int o = 1; o < 1024; o <<= 1) {
        int t = (threadIdx.x >= (unsigned)o) ? sd[threadIdx.x - o] : 0;
        __syncthreads();
        sd[threadIdx.x] += t;
        __syncthreads();
    }
    if (i < n) g_off[i] = sd[threadIdx.x] - v;   // block-local exclusive
    if (threadIdx.x == 1023) g_bsum[blockIdx.x] = sd[1023];
}

__global__ void scan2_kernel(int nb, int n) {   // 1 block, 64 threads
    __shared__ int sd[64];
    int v = (threadIdx.x < (unsigned)nb) ? g_bsum[threadIdx.x] : 0;
    sd[threadIdx.x] = v;
    __syncthreads();
#pragma unroll
    for (int o = 1; o < 64; o <<= 1) {
        int t = (threadIdx.x >= (unsigned)o) ? sd[threadIdx.x - o] : 0;
        __syncthreads();
        sd[threadIdx.x] += t;
        __syncthreads();
    }
    if (threadIdx.x < (unsigned)nb) g_bsum[threadIdx.x] = sd[threadIdx.x] - v;
    if (threadIdx.x == (unsigned)(nb - 1)) g_off[n] = sd[threadIdx.x];
}

__global__ __launch_bounds__(1024) void scan3_kernel(int n) {
    int i = blockIdx.x * 1024 + threadIdx.x;
    if (i < n) {
        int o = g_off[i] + g_bsum[blockIdx.x];
        g_off[i] = o;
        g_cur[i] = o;
    }
}

__global__ void scatter_kernel(const int* __restrict__ ei, int E) {
    int i = blockIdx.x * blockDim.x + threadIdx.x;
    if (i < E) {
        int s = ei[i];
        int d = ei[E + i];
        int p = atomicAdd(&g_cur[d], 1);
        g_esrc[p] = s;
    }
}

// ---------------------------------------------------------------------------
// One warp per destination node: single-pass online segment softmax +
// weighted gather of fp16 features (logits fp32-exact).
// lane l handles flat channels [l*8, l*8+8) -> head = l>>3 (8 lanes/head).
__global__ __launch_bounds__(256) void agg_kernel(
    const float* __restrict__ bias, float* __restrict__ out, int n)
{
    int d = (blockIdx.x * blockDim.x + threadIdx.x) >> 5;
    if (d >= n) return;
    int lane = threadIdx.x & 31;
    int hd = lane >> 3;

    float adst_h = g_adst[d * HEADS + hd];
    int e0 = g_off[d], e1 = g_off[d + 1];

    // self-loop initializes the running state
    float aself = g_asrc[d * HEADS + hd] + adst_h;
    aself = (aself >= 0.f) ? aself : 0.2f * aself;
    float m = aself;
    float denom = 1.f;

    const size_t base = (size_t)d * 256 + lane * 8;
    uint4 raw = *(const uint4*)(g_hf + base);
    float2 f0 = __half22float2(((__half2*)&raw)[0]);
    float2 f1 = __half22float2(((__half2*)&raw)[1]);
    float2 f2 = __half22float2(((__half2*)&raw)[2]);
    float2 f3 = __half22float2(((__half2*)&raw)[3]);
    float acc[8] = { f0.x, f0.y, f1.x, f1.y, f2.x, f2.y, f3.x, f3.y };

    // software-pipelined edge loop (prefetch next a_src)
    int s_next = 0;
    float a_next = 0.f;
    if (e0 < e1) {
        s_next = g_esrc[e0];
        a_next = g_asrc[s_next * HEADS + hd];
    }
    for (int e = e0; e < e1; e++) {
        int s = s_next;
        float a_s = a_next;
        uint4 r = *(const uint4*)(g_hf + (size_t)s * 256 + lane * 8);
        if (e + 1 < e1) {
            s_next = g_esrc[e + 1];
            a_next = g_asrc[s_next * HEADS + hd];
        }
        float al = a_s + adst_h;
        al = (al >= 0.f) ? al : 0.2f * al;
        float mn = fmaxf(m, al);
        float scale = __expf(m - mn);
        float ex = __expf(al - mn);
        m = mn;
        denom = denom * scale + ex;
        float2 w0 = __half22float2(((__half2*)&r)[0]);
        float2 w1 = __half22float2(((__half2*)&r)[1]);
        float2 w2 = __half22float2(((__half2*)&r)[2]);
        float2 w3 = __half22float2(((__half2*)&r)[3]);
        acc[0] = fmaf(acc[0], scale, ex * w0.x);
        acc[1] = fmaf(acc[1], scale, ex * w0.y);
        acc[2] = fmaf(acc[2], scale, ex * w1.x);
        acc[3] = fmaf(acc[3], scale, ex * w1.y);
        acc[4] = fmaf(acc[4], scale, ex * w2.x);
        acc[5] = fmaf(acc[5], scale, ex * w2.y);
        acc[6] = fmaf(acc[6], scale, ex * w3.x);
        acc[7] = fmaf(acc[7], scale, ex * w3.y);
    }

    float inv = 1.f / (denom + 1e-16f);
    float4 b0 = *(const float4*)(bias + lane * 8 + 0);
    float4 b1 = *(const float4*)(bias + lane * 8 + 4);
    float4 o0 = make_float4(acc[0]*inv + b0.x, acc[1]*inv + b0.y,
                            acc[2]*inv + b0.z, acc[3]*inv + b0.w);
    float4 o1 = make_float4(acc[4]*inv + b1.x, acc[5]*inv + b1.y,
                            acc[6]*inv + b1.z, acc[7]*inv + b1.w);
    *(float4*)(out + base + 0) = o0;
    *(float4*)(out + base + 4) = o1;
}

// ---------------------------------------------------------------------------
extern "C" void kernel_launch(void* const* d_in, const int* in_sizes, int n_in,
                              void* d_out, int out_size)
{
    const float* x       = (const float*)d_in[0];
    const int*   ei      = (const int*)d_in[1];     // int32 edge index [2, E]
    const float* W       = (const float*)d_in[2];
    const float* att_src = (const float*)d_in[3];
    const float* att_dst = (const float*)d_in[4];
    const float* bias    = (const float*)d_in[5];
    float*       out     = (float*)d_out;

    int n = in_sizes[0] / 256;      // 50000
    int E = in_sizes[1] / 2;        // 800000
    int nb = (n + 1023) / 1024;
    int nw8 = 256 * 256 / 8;        // W elems / 8

    static int smem_set = 0;        // attribute call is idempotent
    if (!smem_set) {
        cudaFuncSetAttribute(gemm_bf16x3_kernel,
                             cudaFuncAttributeMaxDynamicSharedMemorySize,
                             SMEM_TOT);
        smem_set = 1;
    }

    // Order chosen so the GEMM is the 4th launch (ncu captures index 3).
    zero_kernel<<<(n * HEADS + 255) / 256, 256>>>(n);
    convertW_kernel<<<(nw8 + 255) / 256, 256>>>(W, nw8);
    hist_kernel<<<(E + 255) / 256, 256>>>(ei, E);

    dim3 ggrid(1, (n + BM - 1) / BM);
    gemm_bf16x3_kernel<<<ggrid, 256, SMEM_TOT>>>(x, att_src, att_dst, n);

    scan1_kernel<<<nb, 1024>>>(n);
    scan2_kernel<<<1, 64>>>(nb, n);
    scan3_kernel<<<nb, 1024>>>(n);
    scatter_kernel<<<(E + 255) / 256, 256>>>(ei, E);

    agg_kernel<<<(n * 32 + 255) / 256, 256>>>(bias, out, n);
}

// round 10
// speedup vs baseline: 1.0802x; 1.0802x over previous
#include <cuda_runtime.h>
#include <cuda_bf16.h>
#include <cuda_fp16.h>
#include <cstdint>

// Problem constants (shapes are fixed by the dataset)
#define NN 50000
#define EE 800000
#define HC 256      // HEADS*OUT_C
#define HEADS 4

// Scratch (device globals -- no allocation allowed in kernel_launch)
__device__ __half g_hf[(size_t)NN * HC];          // h in fp16, 25.6 MB
__device__ __nv_bfloat16 g_wh[HC * HC];           // W hi bf16 [k][n]
__device__ __nv_bfloat16 g_wl[HC * HC];           // W lo bf16 [k][n]
__device__ float g_asrc[NN * HEADS];
__device__ float g_adst[NN * HEADS];
__device__ int   g_cnt[NN];
__device__ int   g_off[NN + 1];
__device__ int   g_cur[NN];
__device__ int   g_esrc[EE];
__device__ int   g_bsum[64];

__device__ __forceinline__ void split2(float x, float y,
                                       uint32_t& hi, uint32_t& lo) {
    __nv_bfloat16 hx = __float2bfloat16_rn(x);
    __nv_bfloat16 hy = __float2bfloat16_rn(y);
    __nv_bfloat16 lx = __float2bfloat16_rn(x - __bfloat162float(hx));
    __nv_bfloat16 ly = __float2bfloat16_rn(y - __bfloat162float(hy));
    hi = ((uint32_t)__bfloat16_as_ushort(hy) << 16) | __bfloat16_as_ushort(hx);
    lo = ((uint32_t)__bfloat16_as_ushort(ly) << 16) | __bfloat16_as_ushort(lx);
}

// ---------------------------------------------------------------------------
__global__ void zero_kernel(int n) {
    int i = blockIdx.x * blockDim.x + threadIdx.x;
    if (i < n) g_cnt[i] = 0;
    if (i < n * HEADS) { g_asrc[i] = 0.f; g_adst[i] = 0.f; }
}

// ---------------------------------------------------------------------------
// Preconvert W only (128 KB, reused by all 391 blocks).
__global__ __launch_bounds__(256) void convertW_kernel(
    const float* __restrict__ Wm, int nw8)
{
    int i = blockIdx.x * blockDim.x + threadIdx.x;
    if (i >= nw8) return;
    const float4* src = (const float4*)Wm + (size_t)i * 2;
    float4 v0 = src[0], v1 = src[1];
    uint4 hi, lo;
    split2(v0.x, v0.y, hi.x, lo.x);
    split2(v0.z, v0.w, hi.y, lo.y);
    split2(v1.x, v1.y, hi.z, lo.z);
    split2(v1.z, v1.w, hi.w, lo.w);
    ((uint4*)g_wh)[i] = hi;
    ((uint4*)g_wl)[i] = lo;
}

// ---------------------------------------------------------------------------
// Tensor-core GEMM: h[M,256] = X[M,256] * W[256,256], fp32-equivalent via
// 3-term bf16 split. X read ONCE as fp32, split in-kernel; W preconverted.
// Tile: BM=128, BN=256, BK=32. 16 warps (2x8), warp tile 64x32, m16n8k16.

#define BM 128
#define BN 256
#define BK 32
#define LDA 40    // A smem row stride (bf16): 80B -> conflict-free ldmatrix
#define LDB 264   // B smem row stride (bf16): 528B -> conflict-free .trans
#define SMEM_AH 0
#define SMEM_AL (BM * LDA * 2)                    // 10240
#define SMEM_BH (2 * BM * LDA * 2)                // 20480
#define SMEM_BL (2 * BM * LDA * 2 + BK * LDB * 2) // 37376
#define SMEM_TOT (2 * BM * LDA * 2 + 2 * BK * LDB * 2)  // 54272

__device__ __forceinline__ void mma_bf16(float* c,
    uint32_t a0, uint32_t a1, uint32_t a2, uint32_t a3,
    uint32_t b0, uint32_t b1)
{
    asm volatile(
        "mma.sync.aligned.m16n8k16.row.col.f32.bf16.bf16.f32 "
        "{%0,%1,%2,%3}, {%4,%5,%6,%7}, {%8,%9}, {%0,%1,%2,%3};"
        : "+f"(c[0]), "+f"(c[1]), "+f"(c[2]), "+f"(c[3])
        : "r"(a0), "r"(a1), "r"(a2), "r"(a3), "r"(b0), "r"(b1));
}

__device__ __forceinline__ void ldsm_x4(uint32_t addr, uint32_t* r) {
    asm volatile(
        "ldmatrix.sync.aligned.m8n8.x4.shared.b16 {%0,%1,%2,%3}, [%4];"
        : "=r"(r[0]), "=r"(r[1]), "=r"(r[2]), "=r"(r[3]) : "r"(addr));
}

__device__ __forceinline__ void ldsm_x4_trans(uint32_t addr, uint32_t* r) {
    asm volatile(
        "ldmatrix.sync.aligned.m8n8.x4.trans.shared.b16 {%0,%1,%2,%3}, [%4];"
        : "=r"(r[0]), "=r"(r[1]), "=r"(r[2]), "=r"(r[3]) : "r"(addr));
}

__global__ __launch_bounds__(512) void gemm_bf16x3_kernel(
    const float* __restrict__ X,
    const float* __restrict__ att_src, const float* __restrict__ att_dst,
    int M)
{
    extern __shared__ char smem_raw[];
    __nv_bfloat16* Ah = (__nv_bfloat16*)(smem_raw + SMEM_AH);   // [row][k]
    __nv_bfloat16* Al = (__nv_bfloat16*)(smem_raw + SMEM_AL);
    __nv_bfloat16* Bh = (__nv_bfloat16*)(smem_raw + SMEM_BH);   // [k][n]
    __nv_bfloat16* Bl = (__nv_bfloat16*)(smem_raw + SMEM_BL);

    const int tid  = threadIdx.x;
    const int warp = tid >> 5;
    const int lane = tid & 31;
    const int gid  = lane >> 2;    // row within 8
    const int tig  = lane & 3;     // thread in group
    const int bm = blockIdx.y * BM;
    const int wm = (warp >> 3) * 64;   // 2 rows of warps
    const int wn = (warp & 7) * 32;    // 8 cols of warps

    const uint32_t ah_base = (uint32_t)__cvta_generic_to_shared(Ah);
    const uint32_t al_base = (uint32_t)__cvta_generic_to_shared(Al);
    const uint32_t bh_base = (uint32_t)__cvta_generic_to_shared(Bh);
    const uint32_t bl_base = (uint32_t)__cvta_generic_to_shared(Bl);

    float acc[4][4][4];
#pragma unroll
    for (int mi = 0; mi < 4; mi++)
#pragma unroll
        for (int ni = 0; ni < 4; ni++)
#pragma unroll
            for (int r = 0; r < 4; r++) acc[mi][ni][r] = 0.f;

    // A loader: 4 threads/row, 8 fp32 each. B loader: 16 threads/k-row,
    // 16 n (= 2 uint4 per hi/lo array) each.
    const int a_row = tid >> 2;
    const int a_c   = (tid & 3) * 8;
    const int b_k   = tid >> 4;
    const int b_n   = (tid & 15) * 16;
    const int a_grow = bm + a_row;

    for (int k0 = 0; k0 < 256; k0 += BK) {
        // --- A tile: load X fp32, split to bf16 hi/lo in-kernel ---
        {
            const float4* src =
                (const float4*)(X + (size_t)a_grow * 256 + k0 + a_c);
            int off = a_row * LDA + a_c;
#pragma unroll
            for (int i = 0; i < 2; i++) {
                float4 v = (a_grow < M) ? src[i]
                                        : make_float4(0.f, 0.f, 0.f, 0.f);
                uint32_t h0, l0, h1, l1;
                split2(v.x, v.y, h0, l0);
                split2(v.z, v.w, h1, l1);
                *(uint2*)&Ah[off + i * 4] = make_uint2(h0, h1);
                *(uint2*)&Al[off + i * 4] = make_uint2(l0, l1);
            }
        }
        // --- B tile: preconverted bf16, [k][n]: 16 bf16 = 2 uint4 each ---
        {
            const uint4* sh =
                (const uint4*)(g_wh + (size_t)(k0 + b_k) * 256 + b_n);
            const uint4* sl =
                (const uint4*)(g_wl + (size_t)(k0 + b_k) * 256 + b_n);
            int off = b_k * LDB + b_n;
            *(uint4*)&Bh[off]     = sh[0];
            *(uint4*)&Bh[off + 8] = sh[1];
            *(uint4*)&Bl[off]     = sl[0];
            *(uint4*)&Bl[off + 8] = sl[1];
        }
        __syncthreads();

#pragma unroll
        for (int kk = 0; kk < 2; kk++) {       // two k16 steps per BK
            const int c0 = kk * 16;
            uint32_t ah[4][4], al[4][4], bh[4][2], bl[4][2];
            const uint32_t a_off =
                ((uint32_t)(wm + (lane & 15)) * LDA + c0 + ((lane >> 4) << 3)) * 2;
#pragma unroll
            for (int mi = 0; mi < 4; mi++) {
                ldsm_x4(ah_base + a_off + mi * 16 * LDA * 2, ah[mi]);
                ldsm_x4(al_base + a_off + mi * 16 * LDA * 2, al[mi]);
            }
            const uint32_t b_off =
                ((uint32_t)(c0 + (lane & 15)) * LDB + wn + ((lane >> 4) << 3)) * 2;
#pragma unroll
            for (int nip = 0; nip < 2; nip++) {
                uint32_t t[4];
                ldsm_x4_trans(bh_base + b_off + nip * 16 * 2, t);
                bh[2*nip][0] = t[0]; bh[2*nip][1] = t[1];
                bh[2*nip+1][0] = t[2]; bh[2*nip+1][1] = t[3];
                ldsm_x4_trans(bl_base + b_off + nip * 16 * 2, t);
                bl[2*nip][0] = t[0]; bl[2*nip][1] = t[1];
                bl[2*nip+1][0] = t[2]; bl[2*nip+1][1] = t[3];
            }
#pragma unroll
            for (int mi = 0; mi < 4; mi++)
#pragma unroll
                for (int ni = 0; ni < 4; ni++) {
                    mma_bf16(acc[mi][ni], ah[mi][0], ah[mi][1], ah[mi][2],
                             ah[mi][3], bh[ni][0], bh[ni][1]);
                    mma_bf16(acc[mi][ni], ah[mi][0], ah[mi][1], ah[mi][2],
                             ah[mi][3], bl[ni][0], bl[ni][1]);
                    mma_bf16(acc[mi][ni], al[mi][0], al[mi][1], al[mi][2],
                             al[mi][3], bh[ni][0], bh[ni][1]);
                }
        }
        __syncthreads();
    }

    // --- epilogue: fp16 store of h + fused attention dot partials ---
    const int head = wn >> 6;    // warp's 32-col block lies in one head
#pragma unroll
    for (int mi = 0; mi < 4; mi++) {
        int r0 = bm + wm + mi * 16 + gid;
        int r1 = r0 + 8;
        float ps0 = 0.f, pd0 = 0.f, ps1 = 0.f, pd1 = 0.f;
#pragma unroll
        for (int ni = 0; ni < 4; ni++) {
            int col = wn + ni * 8 + tig * 2;
            float as0 = att_src[col], as1 = att_src[col + 1];
            float ad0 = att_dst[col], ad1 = att_dst[col + 1];
            ps0 += acc[mi][ni][0] * as0 + acc[mi][ni][1] * as1;
            pd0 += acc[mi][ni][0] * ad0 + acc[mi][ni][1] * ad1;
            ps1 += acc[mi][ni][2] * as0 + acc[mi][ni][3] * as1;
            pd1 += acc[mi][ni][2] * ad0 + acc[mi][ni][3] * ad1;
            if (r0 < M)
                *(__half2*)(g_hf + (size_t)r0 * 256 + col) =
                    __floats2half2_rn(acc[mi][ni][0], acc[mi][ni][1]);
            if (r1 < M)
                *(__half2*)(g_hf + (size_t)r1 * 256 + col) =
                    __floats2half2_rn(acc[mi][ni][2], acc[mi][ni][3]);
        }
        // reduce across the 4 tig lanes (same output row) -> 1 atomic per row
        ps0 += __shfl_xor_sync(0xffffffffu, ps0, 1);
        ps0 += __shfl_xor_sync(0xffffffffu, ps0, 2);
        pd0 += __shfl_xor_sync(0xffffffffu, pd0, 1);
        pd0 += __shfl_xor_sync(0xffffffffu, pd0, 2);
        ps1 += __shfl_xor_sync(0xffffffffu, ps1, 1);
        ps1 += __shfl_xor_sync(0xffffffffu, ps1, 2);
        pd1 += __shfl_xor_sync(0xffffffffu, pd1, 1);
        pd1 += __shfl_xor_sync(0xffffffffu, pd1, 2);
        if (tig == 0) {
            if (r0 < M) {
                atomicAdd(&g_asrc[r0 * HEADS + head], ps0);
                atomicAdd(&g_adst[r0 * HEADS + head], pd0);
            }
            if (r1 < M) {
                atomicAdd(&g_asrc[r1 * HEADS + head], ps1);
                atomicAdd(&g_adst[r1 * HEADS + head], pd1);
            }
        }
    }
}

// ---------------------------------------------------------------------------
// edge_index arrives as int32 (JAX x64 disabled -> int64 randint is int32).
__global__ void hist_kernel(const int* __restrict__ ei, int E) {
    int i = blockIdx.x * blockDim.x + threadIdx.x;
    if (i < E) {
        int d = ei[E + i];
        atomicAdd(&g_cnt[d], 1);
    }
}

// ---------------------------------------------------------------------------
// Parallel scan: per-block scan -> block-sums scan -> carry add.
__global__ __launch_bounds__(1024) void scan1_kernel(int n) {
    __shared__ int sd[1024];
    int i = blockIdx.x * 1024 + threadIdx.x;
    int v = (i < n) ? g_cnt[i] : 0;
    sd[threadIdx.x] = v;
    __syncthreads();
#pragma unroll
    for (int o = 1; o < 1024; o <<= 1) {
        int t = (threadIdx.x >= (unsigned)o) ? sd[threadIdx.x - o] : 0;
        __syncthreads();
        sd[threadIdx.x] += t;
        __syncthreads();
    }
    if (i < n) g_off[i] = sd[threadIdx.x] - v;   // block-local exclusive
    if (threadIdx.x == 1023) g_bsum[blockIdx.x] = sd[1023];
}

__global__ void scan2_kernel(int nb, int n) {   // 1 block, 64 threads
    __shared__ int sd[64];
    int v = (threadIdx.x < (unsigned)nb) ? g_bsum[threadIdx.x] : 0;
    sd[threadIdx.x] = v;
    __syncthreads();
#pragma unroll
    for (int o = 1; o < 64; o <<= 1) {
        int t = (threadIdx.x >= (unsigned)o) ? sd[threadIdx.x - o] : 0;
        __syncthreads();
        sd[threadIdx.x] += t;
        __syncthreads();
    }
    if (threadIdx.x < (unsigned)nb) g_bsum[threadIdx.x] = sd[threadIdx.x] - v;
    if (threadIdx.x == (unsigned)(nb - 1)) g_off[n] = sd[threadIdx.x];
}

__global__ __launch_bounds__(1024) void scan3_kernel(int n) {
    int i = blockIdx.x * 1024 + threadIdx.x;
    if (i < n) {
        int o = g_off[i] + g_bsum[blockIdx.x];
        g_off[i] = o;
        g_cur[i] = o;
    }
}

__global__ void scatter_kernel(const int* __restrict__ ei, int E) {
    int i = blockIdx.x * blockDim.x + threadIdx.x;
    if (i < E) {
        int s = ei[i];
        int d = ei[E + i];
        int p = atomicAdd(&g_cur[d], 1);
        g_esrc[p] = s;
    }
}

// ---------------------------------------------------------------------------
// One warp per destination node: single-pass online segment softmax +
// weighted gather of fp16 features (logits fp32-exact).
// lane l handles flat channels [l*8, l*8+8) -> head = l>>3 (8 lanes/head).
__global__ __launch_bounds__(256) void agg_kernel(
    const float* __restrict__ bias, float* __restrict__ out, int n)
{
    int d = (blockIdx.x * blockDim.x + threadIdx.x) >> 5;
    if (d >= n) return;
    int lane = threadIdx.x & 31;
    int hd = lane >> 3;

    float adst_h = g_adst[d * HEADS + hd];
    int e0 = g_off[d], e1 = g_off[d + 1];

    // self-loop initializes the running state
    float aself = g_asrc[d * HEADS + hd] + adst_h;
    aself = (aself >= 0.f) ? aself : 0.2f * aself;
    float m = aself;
    float denom = 1.f;

    const size_t base = (size_t)d * 256 + lane * 8;
    uint4 raw = *(const uint4*)(g_hf + base);
    float2 f0 = __half22float2(((__half2*)&raw)[0]);
    float2 f1 = __half22float2(((__half2*)&raw)[1]);
    float2 f2 = __half22float2(((__half2*)&raw)[2]);
    float2 f3 = __half22float2(((__half2*)&raw)[3]);
    float acc[8] = { f0.x, f0.y, f1.x, f1.y, f2.x, f2.y, f3.x, f3.y };

    // software-pipelined edge loop (prefetch next a_src)
    int s_next = 0;
    float a_next = 0.f;
    if (e0 < e1) {
        s_next = g_esrc[e0];
        a_next = g_asrc[s_next * HEADS + hd];
    }
    for (int e = e0; e < e1; e++) {
        int s = s_next;
        float a_s = a_next;
        uint4 r = *(const uint4*)(g_hf + (size_t)s * 256 + lane * 8);
        if (e + 1 < e1) {
            s_next = g_esrc[e + 1];
            a_next = g_asrc[s_next * HEADS + hd];
        }
        float al = a_s + adst_h;
        al = (al >= 0.f) ? al : 0.2f * al;
        float mn = fmaxf(m, al);
        float scale = __expf(m - mn);
        float ex = __expf(al - mn);
        m = mn;
        denom = denom * scale + ex;
        float2 w0 = __half22float2(((__half2*)&r)[0]);
        float2 w1 = __half22float2(((__half2*)&r)[1]);
        float2 w2 = __half22float2(((__half2*)&r)[2]);
        float2 w3 = __half22float2(((__half2*)&r)[3]);
        acc[0] = fmaf(acc[0], scale, ex * w0.x);
        acc[1] = fmaf(acc[1], scale, ex * w0.y);
        acc[2] = fmaf(acc[2], scale, ex * w1.x);
        acc[3] = fmaf(acc[3], scale, ex * w1.y);
        acc[4] = fmaf(acc[4], scale, ex * w2.x);
        acc[5] = fmaf(acc[5], scale, ex * w2.y);
        acc[6] = fmaf(acc[6], scale, ex * w3.x);
        acc[7] = fmaf(acc[7], scale, ex * w3.y);
    }

    float inv = 1.f / (denom + 1e-16f);
    float4 b0 = *(const float4*)(bias + lane * 8 + 0);
    float4 b1 = *(const float4*)(bias + lane * 8 + 4);
    float4 o0 = make_float4(acc[0]*inv + b0.x, acc[1]*inv + b0.y,
                            acc[2]*inv + b0.z, acc[3]*inv + b0.w);
    float4 o1 = make_float4(acc[4]*inv + b1.x, acc[5]*inv + b1.y,
                            acc[6]*inv + b1.z, acc[7]*inv + b1.w);
    *(float4*)(out + base + 0) = o0;
    *(float4*)(out + base + 4) = o1;
}

// ---------------------------------------------------------------------------
extern "C" void kernel_launch(void* const* d_in, const int* in_sizes, int n_in,
                              void* d_out, int out_size)
{
    const float* x       = (const float*)d_in[0];
    const int*   ei      = (const int*)d_in[1];     // int32 edge index [2, E]
    const float* W       = (const float*)d_in[2];
    const float* att_src = (const float*)d_in[3];
    const float* att_dst = (const float*)d_in[4];
    const float* bias    = (const float*)d_in[5];
    float*       out     = (float*)d_out;

    int n = in_sizes[0] / 256;      // 50000
    int E = in_sizes[1] / 2;        // 800000
    int nb = (n + 1023) / 1024;
    int nw8 = 256 * 256 / 8;        // W elems / 8

    static int smem_set = 0;        // attribute call is idempotent
    if (!smem_set) {
        cudaFuncSetAttribute(gemm_bf16x3_kernel,
                             cudaFuncAttributeMaxDynamicSharedMemorySize,
                             SMEM_TOT);
        smem_set = 1;
    }

    // Order chosen so the GEMM is the 4th launch (ncu captures index 3).
    zero_kernel<<<(n * HEADS + 255) / 256, 256>>>(n);
    convertW_kernel<<<(nw8 + 255) / 256, 256>>>(W, nw8);
    hist_kernel<<<(E + 255) / 256, 256>>>(ei, E);

    dim3 ggrid(1, (n + BM - 1) / BM);
    gemm_bf16x3_kernel<<<ggrid, 512, SMEM_TOT>>>(x, att_src, att_dst, n);

    scan1_kernel<<<nb, 1024>>>(n);
    scan2_kernel<<<1, 64>>>(nb, n);
    scan3_kernel<<<nb, 1024>>>(n);
    scatter_kernel<<<(E + 255) / 256, 256>>>(ei, E);

    agg_kernel<<<(n * 32 + 255) / 256, 256>>>(bias, out, n);
}

// round 11
// speedup vs baseline: 1.0953x; 1.0140x over previous
#include <cuda_runtime.h>
#include <cuda_bf16.h>
#include <cuda_fp16.h>
#include <cstdint>

// Problem constants (shapes are fixed by the dataset)
#define NN 50000
#define EE 800000
#define HC 256      // HEADS*OUT_C
#define HEADS 4

// Scratch (device globals -- no allocation allowed in kernel_launch)
__device__ __half g_hf[(size_t)NN * HC];              // h in fp16, 25.6 MB
__device__ __nv_bfloat16 g_xh[(size_t)(NN + 128) * HC];  // X hi bf16 (+pad)
__device__ __nv_bfloat16 g_xl[(size_t)(NN + 128) * HC];  // X lo bf16 (+pad)
__device__ __nv_bfloat16 g_wh[HC * HC];               // W hi bf16 [k][n]
__device__ __nv_bfloat16 g_wl[HC * HC];               // W lo bf16 [k][n]
__device__ float g_asrc[NN * HEADS];
__device__ float g_adst[NN * HEADS];
__device__ int   g_cnt[NN];
__device__ int   g_off[NN + 1];
__device__ int   g_cur[NN];
__device__ int   g_esrc[EE];
__device__ int   g_bsum[64];

__device__ __forceinline__ void split2(float x, float y,
                                       uint32_t& hi, uint32_t& lo) {
    __nv_bfloat16 hx = __float2bfloat16_rn(x);
    __nv_bfloat16 hy = __float2bfloat16_rn(y);
    __nv_bfloat16 lx = __float2bfloat16_rn(x - __bfloat162float(hx));
    __nv_bfloat16 ly = __float2bfloat16_rn(y - __bfloat162float(hy));
    hi = ((uint32_t)__bfloat16_as_ushort(hy) << 16) | __bfloat16_as_ushort(hx);
    lo = ((uint32_t)__bfloat16_as_ushort(ly) << 16) | __bfloat16_as_ushort(lx);
}

// ---------------------------------------------------------------------------
__global__ void zero_kernel(int n) {
    int i = blockIdx.x * blockDim.x + threadIdx.x;
    if (i < n) g_cnt[i] = 0;
    if (i < n * HEADS) { g_asrc[i] = 0.f; g_adst[i] = 0.f; }
}

// ---------------------------------------------------------------------------
// Preconvert X and W to bf16 hi/lo pairs (one streaming pass).
__global__ __launch_bounds__(256) void convert_kernel(
    const float* __restrict__ X, const float* __restrict__ Wm,
    int nx8, int nw8)
{
    int i = blockIdx.x * blockDim.x + threadIdx.x;
    const float4* src;
    uint4* dh;
    uint4* dl;
    int j;
    if (i < nx8) {
        src = (const float4*)X + (size_t)i * 2;
        dh = (uint4*)g_xh + i;
        dl = (uint4*)g_xl + i;
    } else if ((j = i - nx8) < nw8) {
        src = (const float4*)Wm + (size_t)j * 2;
        dh = (uint4*)g_wh + j;
        dl = (uint4*)g_wl + j;
    } else return;

    float4 v0 = src[0], v1 = src[1];
    uint4 hi, lo;
    split2(v0.x, v0.y, hi.x, lo.x);
    split2(v0.z, v0.w, hi.y, lo.y);
    split2(v1.x, v1.y, hi.z, lo.z);
    split2(v1.z, v1.w, hi.w, lo.w);
    *dh = hi;
    *dl = lo;
}

// ---------------------------------------------------------------------------
// Tensor-core GEMM: h[M,256] = X[M,256] * W[256,256], fp32-equivalent via
// 3-term bf16 split, all operands preconverted. cp.async double-buffered
// tiles, ldmatrix fragments. Epilogue: fp16 h + fused attention dots.
// Tile: BM=128, BN=256, BK=32. 16 warps (2x8), warp tile 64x32, m16n8k16.

#define BM 128
#define BN 256
#define BK 32
#define LDA 40    // A smem row stride (bf16): 80B -> conflict-free ldmatrix
#define LDB 264   // B smem row stride (bf16): 528B -> conflict-free .trans
#define SMEM_AH 0
#define SMEM_AL (BM * LDA * 2)                    // 10240
#define SMEM_BH (2 * BM * LDA * 2)                // 20480
#define SMEM_BL (2 * BM * LDA * 2 + BK * LDB * 2) // 37376
#define SMEM_STAGE (2 * BM * LDA * 2 + 2 * BK * LDB * 2)  // 54272
#define SMEM_TOT (2 * SMEM_STAGE)                 // 108544

__device__ __forceinline__ void mma_bf16(float* c,
    uint32_t a0, uint32_t a1, uint32_t a2, uint32_t a3,
    uint32_t b0, uint32_t b1)
{
    asm volatile(
        "mma.sync.aligned.m16n8k16.row.col.f32.bf16.bf16.f32 "
        "{%0,%1,%2,%3}, {%4,%5,%6,%7}, {%8,%9}, {%0,%1,%2,%3};"
        : "+f"(c[0]), "+f"(c[1]), "+f"(c[2]), "+f"(c[3])
        : "r"(a0), "r"(a1), "r"(a2), "r"(a3), "r"(b0), "r"(b1));
}

__device__ __forceinline__ void ldsm_x4(uint32_t addr, uint32_t* r) {
    asm volatile(
        "ldmatrix.sync.aligned.m8n8.x4.shared.b16 {%0,%1,%2,%3}, [%4];"
        : "=r"(r[0]), "=r"(r[1]), "=r"(r[2]), "=r"(r[3]) : "r"(addr));
}

__device__ __forceinline__ void ldsm_x4_trans(uint32_t addr, uint32_t* r) {
    asm volatile(
        "ldmatrix.sync.aligned.m8n8.x4.trans.shared.b16 {%0,%1,%2,%3}, [%4];"
        : "=r"(r[0]), "=r"(r[1]), "=r"(r[2]), "=r"(r[3]) : "r"(addr));
}

__device__ __forceinline__ void cp_async16(uint32_t smem, const void* gmem) {
    asm volatile("cp.async.cg.shared.global [%0], [%1], 16;"
                 :: "r"(smem), "l"(gmem));
}

__global__ __launch_bounds__(512) void gemm_bf16x3_kernel(
    const float* __restrict__ att_src, const float* __restrict__ att_dst,
    int M)
{
    extern __shared__ char smem_raw[];
    const uint32_t su = (uint32_t)__cvta_generic_to_shared(smem_raw);

    const int tid  = threadIdx.x;
    const int warp = tid >> 5;
    const int lane = tid & 31;
    const int gid  = lane >> 2;    // row within 8
    const int tig  = lane & 3;     // thread in group
    const int bm = blockIdx.y * BM;
    const int wm = (warp >> 3) * 64;   // 2 rows of warps
    const int wn = (warp & 7) * 32;    // 8 cols of warps

    float acc[4][4][4];
#pragma unroll
    for (int mi = 0; mi < 4; mi++)
#pragma unroll
        for (int ni = 0; ni < 4; ni++)
#pragma unroll
            for (int r = 0; r < 4; r++) acc[mi][ni][r] = 0.f;

    // A chunk: tid -> (row, col8): 512 chunks of 8 bf16 cover 128x32.
    const int a_row = tid >> 2;
    const int a_col = (tid & 3) * 8;
    // B chunks: 1024 chunks cover 32x256; 2 per thread.
    const int bk0 = tid >> 5;              // chunk c = tid
    const int bn0 = (tid & 31) * 8;
    const int bk1 = (tid + 512) >> 5;      // chunk c = tid + 512
    const int bn1 = ((tid + 512) & 31) * 8;

    const size_t a_goff = (size_t)(bm + a_row) * 256 + a_col;
    const uint32_t a_soff = (uint32_t)(a_row * LDA + a_col) * 2;
    const uint32_t b_soff0 = (uint32_t)(bk0 * LDB + bn0) * 2;
    const uint32_t b_soff1 = (uint32_t)(bk1 * LDB + bn1) * 2;

#define PREFETCH(it_, buf_)                                                  \
    do {                                                                     \
        int k0_ = (it_) * BK;                                                \
        uint32_t sb_ = su + (buf_) * SMEM_STAGE;                             \
        cp_async16(sb_ + SMEM_AH + a_soff, g_xh + a_goff + k0_);             \
        cp_async16(sb_ + SMEM_AL + a_soff, g_xl + a_goff + k0_);             \
        cp_async16(sb_ + SMEM_BH + b_soff0,                                  \
                   g_wh + (size_t)(k0_ + bk0) * 256 + bn0);                  \
        cp_async16(sb_ + SMEM_BH + b_soff1,                                  \
                   g_wh + (size_t)(k0_ + bk1) * 256 + bn1);                  \
        cp_async16(sb_ + SMEM_BL + b_soff0,                                  \
                   g_wl + (size_t)(k0_ + bk0) * 256 + bn0);                  \
        cp_async16(sb_ + SMEM_BL + b_soff1,                                  \
                   g_wl + (size_t)(k0_ + bk1) * 256 + bn1);                  \
        asm volatile("cp.async.commit_group;");                              \
    } while (0)

    PREFETCH(0, 0);

    for (int it = 0; it < 8; it++) {
        int buf = it & 1;
        if (it < 7) {
            PREFETCH(it + 1, buf ^ 1);
            asm volatile("cp.async.wait_group 1;");
        } else {
            asm volatile("cp.async.wait_group 0;");
        }
        __syncthreads();

        const uint32_t ah_base = su + buf * SMEM_STAGE + SMEM_AH;
        const uint32_t al_base = su + buf * SMEM_STAGE + SMEM_AL;
        const uint32_t bh_base = su + buf * SMEM_STAGE + SMEM_BH;
        const uint32_t bl_base = su + buf * SMEM_STAGE + SMEM_BL;

#pragma unroll
        for (int kk = 0; kk < 2; kk++) {       // two k16 steps per BK
            const int c0 = kk * 16;
            uint32_t ah[4][4], al[4][4], bh[4][2], bl[4][2];
            const uint32_t a_off =
                ((uint32_t)(wm + (lane & 15)) * LDA + c0 + ((lane >> 4) << 3)) * 2;
#pragma unroll
            for (int mi = 0; mi < 4; mi++) {
                ldsm_x4(ah_base + a_off + mi * 16 * LDA * 2, ah[mi]);
                ldsm_x4(al_base + a_off + mi * 16 * LDA * 2, al[mi]);
            }
            const uint32_t b_off =
                ((uint32_t)(c0 + (lane & 15)) * LDB + wn + ((lane >> 4) << 3)) * 2;
#pragma unroll
            for (int nip = 0; nip < 2; nip++) {
                uint32_t t[4];
                ldsm_x4_trans(bh_base + b_off + nip * 16 * 2, t);
                bh[2*nip][0] = t[0]; bh[2*nip][1] = t[1];
                bh[2*nip+1][0] = t[2]; bh[2*nip+1][1] = t[3];
                ldsm_x4_trans(bl_base + b_off + nip * 16 * 2, t);
                bl[2*nip][0] = t[0]; bl[2*nip][1] = t[1];
                bl[2*nip+1][0] = t[2]; bl[2*nip+1][1] = t[3];
            }
#pragma unroll
            for (int mi = 0; mi < 4; mi++)
#pragma unroll
                for (int ni = 0; ni < 4; ni++) {
                    mma_bf16(acc[mi][ni], ah[mi][0], ah[mi][1], ah[mi][2],
                             ah[mi][3], bh[ni][0], bh[ni][1]);
                    mma_bf16(acc[mi][ni], ah[mi][0], ah[mi][1], ah[mi][2],
                             ah[mi][3], bl[ni][0], bl[ni][1]);
                    mma_bf16(acc[mi][ni], al[mi][0], al[mi][1], al[mi][2],
                             al[mi][3], bh[ni][0], bh[ni][1]);
                }
        }
        __syncthreads();
    }

    // --- epilogue: fp16 store of h + fused attention dot partials ---
    const int head = wn >> 6;    // warp's 32-col block lies in one head
#pragma unroll
    for (int mi = 0; mi < 4; mi++) {
        int r0 = bm + wm + mi * 16 + gid;
        int r1 = r0 + 8;
        float ps0 = 0.f, pd0 = 0.f, ps1 = 0.f, pd1 = 0.f;
#pragma unroll
        for (int ni = 0; ni < 4; ni++) {
            int col = wn + ni * 8 + tig * 2;
            float as0 = att_src[col], as1 = att_src[col + 1];
            float ad0 = att_dst[col], ad1 = att_dst[col + 1];
            ps0 += acc[mi][ni][0] * as0 + acc[mi][ni][1] * as1;
            pd0 += acc[mi][ni][0] * ad0 + acc[mi][ni][1] * ad1;
            ps1 += acc[mi][ni][2] * as0 + acc[mi][ni][3] * as1;
            pd1 += acc[mi][ni][2] * ad0 + acc[mi][ni][3] * ad1;
            if (r0 < M)
                *(__half2*)(g_hf + (size_t)r0 * 256 + col) =
                    __floats2half2_rn(acc[mi][ni][0], acc[mi][ni][1]);
            if (r1 < M)
                *(__half2*)(g_hf + (size_t)r1 * 256 + col) =
                    __floats2half2_rn(acc[mi][ni][2], acc[mi][ni][3]);
        }
        // reduce across the 4 tig lanes (same output row) -> 1 atomic per row
        ps0 += __shfl_xor_sync(0xffffffffu, ps0, 1);
        ps0 += __shfl_xor_sync(0xffffffffu, ps0, 2);
        pd0 += __shfl_xor_sync(0xffffffffu, pd0, 1);
        pd0 += __shfl_xor_sync(0xffffffffu, pd0, 2);
        ps1 += __shfl_xor_sync(0xffffffffu, ps1, 1);
        ps1 += __shfl_xor_sync(0xffffffffu, ps1, 2);
        pd1 += __shfl_xor_sync(0xffffffffu, pd1, 1);
        pd1 += __shfl_xor_sync(0xffffffffu, pd1, 2);
        if (tig == 0) {
            if (r0 < M) {
                atomicAdd(&g_asrc[r0 * HEADS + head], ps0);
                atomicAdd(&g_adst[r0 * HEADS + head], pd0);
            }
            if (r1 < M) {
                atomicAdd(&g_asrc[r1 * HEADS + head], ps1);
                atomicAdd(&g_adst[r1 * HEADS + head], pd1);
            }
        }
    }
}

// ---------------------------------------------------------------------------
// edge_index arrives as int32 (JAX x64 disabled -> int64 randint is int32).
__global__ void hist_kernel(const int* __restrict__ ei, int E) {
    int i = blockIdx.x * blockDim.x + threadIdx.x;
    if (i < E) {
        int d = ei[E + i];
        atomicAdd(&g_cnt[d], 1);
    }
}

// ---------------------------------------------------------------------------
// Parallel scan: per-block scan -> block-sums scan -> carry add.
__global__ __launch_bounds__(1024) void scan1_kernel(int n) {
    __shared__ int sd[1024];
    int i = blockIdx.x * 1024 + threadIdx.x;
    int v = (i < n) ? g_cnt[i] : 0;
    sd[threadIdx.x] = v;
    __syncthreads();
#pragma unroll
    for (int o = 1; o < 1024; o <<= 1) {
        int t = (threadIdx.x >= (unsigned)o) ? sd[threadIdx.x - o] : 0;
        __syncthreads();
        sd[threadIdx.x] += t;
        __syncthreads();
    }
    if (i < n) g_off[i] = sd[threadIdx.x] - v;   // block-local exclusive
    if (threadIdx.x == 1023) g_bsum[blockIdx.x] = sd[1023];
}

__global__ void scan2_kernel(int nb, int n) {   // 1 block, 64 threads
    __shared__ int sd[64];
    int v = (threadIdx.x < (unsigned)nb) ? g_bsum[threadIdx.x] : 0;
    sd[threadIdx.x] = v;
    __syncthreads();
#pragma unroll
    for (int o = 1; o < 64; o <<= 1) {
        int t = (threadIdx.x >= (unsigned)o) ? sd[threadIdx.x - o] : 0;
        __syncthreads();
        sd[threadIdx.x] += t;
        __syncthreads();
    }
    if (threadIdx.x < (unsigned)nb) g_bsum[threadIdx.x] = sd[threadIdx.x] - v;
    if (threadIdx.x == (unsigned)(nb - 1)) g_off[n] = sd[threadIdx.x];
}

__global__ __launch_bounds__(1024) void scan3_kernel(int n) {
    int i = blockIdx.x * 1024 + threadIdx.x;
    if (i < n) {
        int o = g_off[i] + g_bsum[blockIdx.x];
        g_off[i] = o;
        g_cur[i] = o;
    }
}

__global__ void scatter_kernel(const int* __restrict__ ei, int E) {
    int i = blockIdx.x * blockDim.x + threadIdx.x;
    if (i < E) {
        int s = ei[i];
        int d = ei[E + i];
        int p = atomicAdd(&g_cur[d], 1);
        g_esrc[p] = s;
    }
}

// ---------------------------------------------------------------------------
// One warp per destination node: single-pass online segment softmax +
// weighted gather of fp16 features (logits fp32-exact).
// lane l handles flat channels [l*8, l*8+8) -> head = l>>3 (8 lanes/head).
__global__ __launch_bounds__(256) void agg_kernel(
    const float* __restrict__ bias, float* __restrict__ out, int n)
{
    int d = (blockIdx.x * blockDim.x + threadIdx.x) >> 5;
    if (d >= n) return;
    int lane = threadIdx.x & 31;
    int hd = lane >> 3;

    float adst_h = g_adst[d * HEADS + hd];
    int e0 = g_off[d], e1 = g_off[d + 1];

    // self-loop initializes the running state
    float aself = g_asrc[d * HEADS + hd] + adst_h;
    aself = (aself >= 0.f) ? aself : 0.2f * aself;
    float m = aself;
    float denom = 1.f;

    const size_t base = (size_t)d * 256 + lane * 8;
    uint4 raw = *(const uint4*)(g_hf + base);
    float2 f0 = __half22float2(((__half2*)&raw)[0]);
    float2 f1 = __half22float2(((__half2*)&raw)[1]);
    float2 f2 = __half22float2(((__half2*)&raw)[2]);
    float2 f3 = __half22float2(((__half2*)&raw)[3]);
    float acc[8] = { f0.x, f0.y, f1.x, f1.y, f2.x, f2.y, f3.x, f3.y };

    // software-pipelined edge loop (prefetch next a_src)
    int s_next = 0;
    float a_next = 0.f;
    if (e0 < e1) {
        s_next = g_esrc[e0];
        a_next = g_asrc[s_next * HEADS + hd];
    }
    for (int e = e0; e < e1; e++) {
        int s = s_next;
        float a_s = a_next;
        uint4 r = *(const uint4*)(g_hf + (size_t)s * 256 + lane * 8);
        if (e + 1 < e1) {
            s_next = g_esrc[e + 1];
            a_next = g_asrc[s_next * HEADS + hd];
        }
        float al = a_s + adst_h;
        al = (al >= 0.f) ? al : 0.2f * al;
        float mn = fmaxf(m, al);
        float scale = __expf(m - mn);
        float ex = __expf(al - mn);
        m = mn;
        denom = denom * scale + ex;
        float2 w0 = __half22float2(((__half2*)&r)[0]);
        float2 w1 = __half22float2(((__half2*)&r)[1]);
        float2 w2 = __half22float2(((__half2*)&r)[2]);
        float2 w3 = __half22float2(((__half2*)&r)[3]);
        acc[0] = fmaf(acc[0], scale, ex * w0.x);
        acc[1] = fmaf(acc[1], scale, ex * w0.y);
        acc[2] = fmaf(acc[2], scale, ex * w1.x);
        acc[3] = fmaf(acc[3], scale, ex * w1.y);
        acc[4] = fmaf(acc[4], scale, ex * w2.x);
        acc[5] = fmaf(acc[5], scale, ex * w2.y);
        acc[6] = fmaf(acc[6], scale, ex * w3.x);
        acc[7] = fmaf(acc[7], scale, ex * w3.y);
    }

    float inv = 1.f / (denom + 1e-16f);
    float4 b0 = *(const float4*)(bias + lane * 8 + 0);
    float4 b1 = *(const float4*)(bias + lane * 8 + 4);
    float4 o0 = make_float4(acc[0]*inv + b0.x, acc[1]*inv + b0.y,
                            acc[2]*inv + b0.z, acc[3]*inv + b0.w);
    float4 o1 = make_float4(acc[4]*inv + b1.x, acc[5]*inv + b1.y,
                            acc[6]*inv + b1.z, acc[7]*inv + b1.w);
    *(float4*)(out + base + 0) = o0;
    *(float4*)(out + base + 4) = o1;
}

// ---------------------------------------------------------------------------
extern "C" void kernel_launch(void* const* d_in, const int* in_sizes, int n_in,
                              void* d_out, int out_size)
{
    const float* x       = (const float*)d_in[0];
    const int*   ei      = (const int*)d_in[1];     // int32 edge index [2, E]
    const float* W       = (const float*)d_in[2];
    const float* att_src = (const float*)d_in[3];
    const float* att_dst = (const float*)d_in[4];
    const float* bias    = (const float*)d_in[5];
    float*       out     = (float*)d_out;

    int n = in_sizes[0] / 256;      // 50000
    int E = in_sizes[1] / 2;        // 800000
    int nb = (n + 1023) / 1024;
    int nx8 = n * 256 / 8;
    int nw8 = 256 * 256 / 8;

    static int smem_set = 0;        // attribute call is idempotent
    if (!smem_set) {
        cudaFuncSetAttribute(gemm_bf16x3_kernel,
                             cudaFuncAttributeMaxDynamicSharedMemorySize,
                             SMEM_TOT);
        smem_set = 1;
    }

    // Order chosen so the GEMM is the 4th launch (ncu captures index 3).
    zero_kernel<<<(n * HEADS + 255) / 256, 256>>>(n);
    convert_kernel<<<(nx8 + nw8 + 255) / 256, 256>>>(x, W, nx8, nw8);
    hist_kernel<<<(E + 255) / 256, 256>>>(ei, E);

    dim3 ggrid(1, (n + BM - 1) / BM);
    gemm_bf16x3_kernel<<<ggrid, 512, SMEM_TOT>>>(att_src, att_dst, n);

    scan1_kernel<<<nb, 1024>>>(n);
    scan2_kernel<<<1, 64>>>(nb, n);
    scan3_kernel<<<nb, 1024>>>(n);
    scatter_kernel<<<(E + 255) / 256, 256>>>(ei, E);

    agg_kernel<<<(n * 32 + 255) / 256, 256>>>(bias, out, n);
}

// round 12
// speedup vs baseline: 1.2507x; 1.1419x over previous
#include <cuda_runtime.h>
#include <cuda_bf16.h>
#include <cuda_fp16.h>
#include <cstdint>

// Problem constants (shapes are fixed by the dataset)
#define NN 50000
#define EE 800000
#define HC 256      // HEADS*OUT_C
#define HEADS 4

// Scratch (device globals -- no allocation allowed in kernel_launch)
__device__ __half g_hf[(size_t)NN * HC];              // h in fp16, 25.6 MB
__device__ __nv_bfloat16 g_xh[(size_t)(NN + 128) * HC];  // X hi bf16 (+pad)
__device__ __nv_bfloat16 g_xl[(size_t)(NN + 128) * HC];  // X lo bf16 (+pad)
__device__ __nv_bfloat16 g_wh[HC * HC];               // W hi bf16 [k][n]
__device__ __nv_bfloat16 g_wl[HC * HC];               // W lo bf16 [k][n]
__device__ float g_asrc[NN * HEADS];
__device__ float g_adst[NN * HEADS];
__device__ int   g_cnt[NN];
__device__ int   g_off[NN + 1];
__device__ int   g_cur[NN];
__device__ int   g_esrc[EE];
__device__ int   g_bsum[64];

__device__ __forceinline__ void split2(float x, float y,
                                       uint32_t& hi, uint32_t& lo) {
    __nv_bfloat16 hx = __float2bfloat16_rn(x);
    __nv_bfloat16 hy = __float2bfloat16_rn(y);
    __nv_bfloat16 lx = __float2bfloat16_rn(x - __bfloat162float(hx));
    __nv_bfloat16 ly = __float2bfloat16_rn(y - __bfloat162float(hy));
    hi = ((uint32_t)__bfloat16_as_ushort(hy) << 16) | __bfloat16_as_ushort(hx);
    lo = ((uint32_t)__bfloat16_as_ushort(ly) << 16) | __bfloat16_as_ushort(lx);
}

// ---------------------------------------------------------------------------
__global__ void zero_kernel(int n) {
    int i = blockIdx.x * blockDim.x + threadIdx.x;
    if (i < n) g_cnt[i] = 0;
    if (i < n * HEADS) { g_asrc[i] = 0.f; g_adst[i] = 0.f; }
}

// ---------------------------------------------------------------------------
// Preconvert X and W to bf16 hi/lo pairs (one streaming pass).
__global__ __launch_bounds__(256) void convert_kernel(
    const float* __restrict__ X, const float* __restrict__ Wm,
    int nx8, int nw8)
{
    int i = blockIdx.x * blockDim.x + threadIdx.x;
    const float4* src;
    uint4* dh;
    uint4* dl;
    int j;
    if (i < nx8) {
        src = (const float4*)X + (size_t)i * 2;
        dh = (uint4*)g_xh + i;
        dl = (uint4*)g_xl + i;
    } else if ((j = i - nx8) < nw8) {
        src = (const float4*)Wm + (size_t)j * 2;
        dh = (uint4*)g_wh + j;
        dl = (uint4*)g_wl + j;
    } else return;

    float4 v0 = src[0], v1 = src[1];
    uint4 hi, lo;
    split2(v0.x, v0.y, hi.x, lo.x);
    split2(v0.z, v0.w, hi.y, lo.y);
    split2(v1.x, v1.y, hi.z, lo.z);
    split2(v1.z, v1.w, hi.w, lo.w);
    *dh = hi;
    *dl = lo;
}

// ---------------------------------------------------------------------------
// Tensor-core GEMM: h[M,256] = X[M,256] * W[256,256], fp32-equivalent via
// 3-term bf16 split, all operands preconverted. 3-stage cp.async pipeline,
// ldmatrix fragments. Epilogue: fp16 h + fused attention dots.
// Tile: BM=128, BN=256, BK=32. 16 warps (2x8), warp tile 64x32, m16n8k16.

#define BM 128
#define BN 256
#define BK 32
#define LDA 40    // A smem row stride (bf16): 80B -> conflict-free ldmatrix
#define LDB 264   // B smem row stride (bf16): 528B -> conflict-free .trans
#define SMEM_AH 0
#define SMEM_AL (BM * LDA * 2)                    // 10240
#define SMEM_BH (2 * BM * LDA * 2)                // 20480
#define SMEM_BL (2 * BM * LDA * 2 + BK * LDB * 2) // 37376
#define SMEM_STAGE (2 * BM * LDA * 2 + 2 * BK * LDB * 2)  // 54272
#define SMEM_TOT (3 * SMEM_STAGE)                 // 162816

__device__ __forceinline__ void mma_bf16(float* c,
    uint32_t a0, uint32_t a1, uint32_t a2, uint32_t a3,
    uint32_t b0, uint32_t b1)
{
    asm volatile(
        "mma.sync.aligned.m16n8k16.row.col.f32.bf16.bf16.f32 "
        "{%0,%1,%2,%3}, {%4,%5,%6,%7}, {%8,%9}, {%0,%1,%2,%3};"
        : "+f"(c[0]), "+f"(c[1]), "+f"(c[2]), "+f"(c[3])
        : "r"(a0), "r"(a1), "r"(a2), "r"(a3), "r"(b0), "r"(b1));
}

__device__ __forceinline__ void ldsm_x4(uint32_t addr, uint32_t* r) {
    asm volatile(
        "ldmatrix.sync.aligned.m8n8.x4.shared.b16 {%0,%1,%2,%3}, [%4];"
        : "=r"(r[0]), "=r"(r[1]), "=r"(r[2]), "=r"(r[3]) : "r"(addr));
}

__device__ __forceinline__ void ldsm_x4_trans(uint32_t addr, uint32_t* r) {
    asm volatile(
        "ldmatrix.sync.aligned.m8n8.x4.trans.shared.b16 {%0,%1,%2,%3}, [%4];"
        : "=r"(r[0]), "=r"(r[1]), "=r"(r[2]), "=r"(r[3]) : "r"(addr));
}

__device__ __forceinline__ void cp_async16(uint32_t smem, const void* gmem) {
    asm volatile("cp.async.cg.shared.global [%0], [%1], 16;"
                 :: "r"(smem), "l"(gmem));
}

__global__ __launch_bounds__(512) void gemm_bf16x3_kernel(
    const float* __restrict__ att_src, const float* __restrict__ att_dst,
    int M)
{
    extern __shared__ char smem_raw[];
    const uint32_t su = (uint32_t)__cvta_generic_to_shared(smem_raw);

    const int tid  = threadIdx.x;
    const int warp = tid >> 5;
    const int lane = tid & 31;
    const int gid  = lane >> 2;    // row within 8
    const int tig  = lane & 3;     // thread in group
    const int bm = blockIdx.y * BM;
    const int wm = (warp >> 3) * 64;   // 2 rows of warps
    const int wn = (warp & 7) * 32;    // 8 cols of warps

    float acc[4][4][4];
#pragma unroll
    for (int mi = 0; mi < 4; mi++)
#pragma unroll
        for (int ni = 0; ni < 4; ni++)
#pragma unroll
            for (int r = 0; r < 4; r++) acc[mi][ni][r] = 0.f;

    // A chunk: tid -> (row, col8): 512 chunks of 8 bf16 cover 128x32.
    const int a_row = tid >> 2;
    const int a_col = (tid & 3) * 8;
    // B chunks: 1024 chunks cover 32x256; 2 per thread.
    const int bk0 = tid >> 5;
    const int bn0 = (tid & 31) * 8;
    const int bk1 = (tid + 512) >> 5;
    const int bn1 = ((tid + 512) & 31) * 8;

    const size_t a_goff = (size_t)(bm + a_row) * 256 + a_col;
    const uint32_t a_soff = (uint32_t)(a_row * LDA + a_col) * 2;
    const uint32_t b_soff0 = (uint32_t)(bk0 * LDB + bn0) * 2;
    const uint32_t b_soff1 = (uint32_t)(bk1 * LDB + bn1) * 2;

#define PREFETCH(it_, buf_)                                                  \
    do {                                                                     \
        int k0_ = (it_) * BK;                                                \
        uint32_t sb_ = su + (buf_) * SMEM_STAGE;                             \
        cp_async16(sb_ + SMEM_AH + a_soff, g_xh + a_goff + k0_);             \
        cp_async16(sb_ + SMEM_AL + a_soff, g_xl + a_goff + k0_);             \
        cp_async16(sb_ + SMEM_BH + b_soff0,                                  \
                   g_wh + (size_t)(k0_ + bk0) * 256 + bn0);                  \
        cp_async16(sb_ + SMEM_BH + b_soff1,                                  \
                   g_wh + (size_t)(k0_ + bk1) * 256 + bn1);                  \
        cp_async16(sb_ + SMEM_BL + b_soff0,                                  \
                   g_wl + (size_t)(k0_ + bk0) * 256 + bn0);                  \
        cp_async16(sb_ + SMEM_BL + b_soff1,                                  \
                   g_wl + (size_t)(k0_ + bk1) * 256 + bn1);                  \
        asm volatile("cp.async.commit_group;");                              \
    } while (0)

    PREFETCH(0, 0);
    PREFETCH(1, 1);

    for (int it = 0; it < 8; it++) {
        int buf = it % 3;
        if (it + 2 < 8) {
            PREFETCH(it + 2, (it + 2) % 3);
            asm volatile("cp.async.wait_group 2;");
        } else if (it + 1 < 8) {
            asm volatile("cp.async.wait_group 1;");
        } else {
            asm volatile("cp.async.wait_group 0;");
        }
        __syncthreads();

        const uint32_t ah_base = su + buf * SMEM_STAGE + SMEM_AH;
        const uint32_t al_base = su + buf * SMEM_STAGE + SMEM_AL;
        const uint32_t bh_base = su + buf * SMEM_STAGE + SMEM_BH;
        const uint32_t bl_base = su + buf * SMEM_STAGE + SMEM_BL;

#pragma unroll
        for (int kk = 0; kk < 2; kk++) {       // two k16 steps per BK
            const int c0 = kk * 16;
            uint32_t ah[4][4], al[4][4], bh[4][2], bl[4][2];
            const uint32_t a_off =
                ((uint32_t)(wm + (lane & 15)) * LDA + c0 + ((lane >> 4) << 3)) * 2;
#pragma unroll
            for (int mi = 0; mi < 4; mi++) {
                ldsm_x4(ah_base + a_off + mi * 16 * LDA * 2, ah[mi]);
                ldsm_x4(al_base + a_off + mi * 16 * LDA * 2, al[mi]);
            }
            const uint32_t b_off =
                ((uint32_t)(c0 + (lane & 15)) * LDB + wn + ((lane >> 4) << 3)) * 2;
#pragma unroll
            for (int nip = 0; nip < 2; nip++) {
                uint32_t t[4];
                ldsm_x4_trans(bh_base + b_off + nip * 16 * 2, t);
                bh[2*nip][0] = t[0]; bh[2*nip][1] = t[1];
                bh[2*nip+1][0] = t[2]; bh[2*nip+1][1] = t[3];
                ldsm_x4_trans(bl_base + b_off + nip * 16 * 2, t);
                bl[2*nip][0] = t[0]; bl[2*nip][1] = t[1];
                bl[2*nip+1][0] = t[2]; bl[2*nip+1][1] = t[3];
            }
#pragma unroll
            for (int mi = 0; mi < 4; mi++)
#pragma unroll
                for (int ni = 0; ni < 4; ni++) {
                    mma_bf16(acc[mi][ni], ah[mi][0], ah[mi][1], ah[mi][2],
                             ah[mi][3], bh[ni][0], bh[ni][1]);
                    mma_bf16(acc[mi][ni], ah[mi][0], ah[mi][1], ah[mi][2],
                             ah[mi][3], bl[ni][0], bl[ni][1]);
                    mma_bf16(acc[mi][ni], al[mi][0], al[mi][1], al[mi][2],
                             al[mi][3], bh[ni][0], bh[ni][1]);
                }
        }
        __syncthreads();
    }

    // --- epilogue: fp16 store of h + fused attention dot partials ---
    const int head = wn >> 6;    // warp's 32-col block lies in one head
#pragma unroll
    for (int mi = 0; mi < 4; mi++) {
        int r0 = bm + wm + mi * 16 + gid;
        int r1 = r0 + 8;
        float ps0 = 0.f, pd0 = 0.f, ps1 = 0.f, pd1 = 0.f;
#pragma unroll
        for (int ni = 0; ni < 4; ni++) {
            int col = wn + ni * 8 + tig * 2;
            float as0 = att_src[col], as1 = att_src[col + 1];
            float ad0 = att_dst[col], ad1 = att_dst[col + 1];
            ps0 += acc[mi][ni][0] * as0 + acc[mi][ni][1] * as1;
            pd0 += acc[mi][ni][0] * ad0 + acc[mi][ni][1] * ad1;
            ps1 += acc[mi][ni][2] * as0 + acc[mi][ni][3] * as1;
            pd1 += acc[mi][ni][2] * ad0 + acc[mi][ni][3] * ad1;
            if (r0 < M)
                *(__half2*)(g_hf + (size_t)r0 * 256 + col) =
                    __floats2half2_rn(acc[mi][ni][0], acc[mi][ni][1]);
            if (r1 < M)
                *(__half2*)(g_hf + (size_t)r1 * 256 + col) =
                    __floats2half2_rn(acc[mi][ni][2], acc[mi][ni][3]);
        }
        // reduce across the 4 tig lanes (same output row) -> 1 atomic per row
        ps0 += __shfl_xor_sync(0xffffffffu, ps0, 1);
        ps0 += __shfl_xor_sync(0xffffffffu, ps0, 2);
        pd0 += __shfl_xor_sync(0xffffffffu, pd0, 1);
        pd0 += __shfl_xor_sync(0xffffffffu, pd0, 2);
        ps1 += __shfl_xor_sync(0xffffffffu, ps1, 1);
        ps1 += __shfl_xor_sync(0xffffffffu, ps1, 2);
        pd1 += __shfl_xor_sync(0xffffffffu, pd1, 1);
        pd1 += __shfl_xor_sync(0xffffffffu, pd1, 2);
        if (tig == 0) {
            if (r0 < M) {
                atomicAdd(&g_asrc[r0 * HEADS + head], ps0);
                atomicAdd(&g_adst[r0 * HEADS + head], pd0);
            }
            if (r1 < M) {
                atomicAdd(&g_asrc[r1 * HEADS + head], ps1);
                atomicAdd(&g_adst[r1 * HEADS + head], pd1);
            }
        }
    }
}

// ---------------------------------------------------------------------------
// edge_index arrives as int32 (JAX x64 disabled -> int64 randint is int32).
__global__ void hist_kernel(const int* __restrict__ ei, int E) {
    int i = blockIdx.x * blockDim.x + threadIdx.x;
    if (i < E) {
        int d = ei[E + i];
        atomicAdd(&g_cnt[d], 1);
    }
}

// ---------------------------------------------------------------------------
// Parallel scan: per-block scan -> block-sums scan -> carry add.
__global__ __launch_bounds__(1024) void scan1_kernel(int n) {
    __shared__ int sd[1024];
    int i = blockIdx.x * 1024 + threadIdx.x;
    int v = (i < n) ? g_cnt[i] : 0;
    sd[threadIdx.x] = v;
    __syncthreads();
#pragma unroll
    for (int o = 1; o < 1024; o <<= 1) {
        int t = (threadIdx.x >= (unsigned)o) ? sd[threadIdx.x - o] : 0;
        __syncthreads();
        sd[threadIdx.x] += t;
        __syncthreads();
    }
    if (i < n) g_off[i] = sd[threadIdx.x] - v;   // block-local exclusive
    if (threadIdx.x == 1023) g_bsum[blockIdx.x] = sd[1023];
}

__global__ void scan2_kernel(int nb, int n) {   // 1 block, 64 threads
    __shared__ int sd[64];
    int v = (threadIdx.x < (unsigned)nb) ? g_bsum[threadIdx.x] : 0;
    sd[threadIdx.x] = v;
    __syncthreads();
#pragma unroll
    for (int o = 1; o < 64; o <<= 1) {
        int t = (threadIdx.x >= (unsigned)o) ? sd[threadIdx.x - o] : 0;
        __syncthreads();
        sd[threadIdx.x] += t;
        __syncthreads();
    }
    if (threadIdx.x < (unsigned)nb) g_bsum[threadIdx.x] = sd[threadIdx.x] - v;
    if (threadIdx.x == (unsigned)(nb - 1)) g_off[n] = sd[threadIdx.x];
}

__global__ __launch_bounds__(1024) void scan3_kernel(int n) {
    int i = blockIdx.x * 1024 + threadIdx.x;
    if (i < n) {
        int o = g_off[i] + g_bsum[blockIdx.x];
        g_off[i] = o;
        g_cur[i] = o;
    }
}

__global__ void scatter_kernel(const int* __restrict__ ei, int E) {
    int i = blockIdx.x * blockDim.x + threadIdx.x;
    if (i < E) {
        int s = ei[i];
        int d = ei[E + i];
        int p = atomicAdd(&g_cur[d], 1);
        g_esrc[p] = s;
    }
}

// ---------------------------------------------------------------------------
// One warp per destination node: single-pass online segment softmax +
// weighted gather of fp16 features (logits fp32-exact).
// lane l handles flat channels [l*8, l*8+8) -> head = l>>3 (8 lanes/head).
__global__ __launch_bounds__(256) void agg_kernel(
    const float* __restrict__ bias, float* __restrict__ out, int n)
{
    int d = (blockIdx.x * blockDim.x + threadIdx.x) >> 5;
    if (d >= n) return;
    int lane = threadIdx.x & 31;
    int hd = lane >> 3;

    float adst_h = g_adst[d * HEADS + hd];
    int e0 = g_off[d], e1 = g_off[d + 1];

    // self-loop initializes the running state
    float aself = g_asrc[d * HEADS + hd] + adst_h;
    aself = (aself >= 0.f) ? aself : 0.2f * aself;
    float m = aself;
    float denom = 1.f;

    const size_t base = (size_t)d * 256 + lane * 8;
    uint4 raw = *(const uint4*)(g_hf + base);
    float2 f0 = __half22float2(((__half2*)&raw)[0]);
    float2 f1 = __half22float2(((__half2*)&raw)[1]);
    float2 f2 = __half22float2(((__half2*)&raw)[2]);
    float2 f3 = __half22float2(((__half2*)&raw)[3]);
    float acc[8] = { f0.x, f0.y, f1.x, f1.y, f2.x, f2.y, f3.x, f3.y };

    // software-pipelined edge loop (prefetch next a_src)
    int s_next = 0;
    float a_next = 0.f;
    if (e0 < e1) {
        s_next = g_esrc[e0];
        a_next = g_asrc[s_next * HEADS + hd];
    }
    for (int e = e0; e < e1; e++) {
        int s = s_next;
        float a_s = a_next;
        uint4 r = *(const uint4*)(g_hf + (size_t)s * 256 + lane * 8);
        if (e + 1 < e1) {
            s_next = g_esrc[e + 1];
            a_next = g_asrc[s_next * HEADS + hd];
        }
        float al = a_s + adst_h;
        al = (al >= 0.f) ? al : 0.2f * al;
        float mn = fmaxf(m, al);
        float scale = __expf(m - mn);
        float ex = __expf(al - mn);
        m = mn;
        denom = denom * scale + ex;
        float2 w0 = __half22float2(((__half2*)&r)[0]);
        float2 w1 = __half22float2(((__half2*)&r)[1]);
        float2 w2 = __half22float2(((__half2*)&r)[2]);
        float2 w3 = __half22float2(((__half2*)&r)[3]);
        acc[0] = fmaf(acc[0], scale, ex * w0.x);
        acc[1] = fmaf(acc[1], scale, ex * w0.y);
        acc[2] = fmaf(acc[2], scale, ex * w1.x);
        acc[3] = fmaf(acc[3], scale, ex * w1.y);
        acc[4] = fmaf(acc[4], scale, ex * w2.x);
        acc[5] = fmaf(acc[5], scale, ex * w2.y);
        acc[6] = fmaf(acc[6], scale, ex * w3.x);
        acc[7] = fmaf(acc[7], scale, ex * w3.y);
    }

    float inv = 1.f / (denom + 1e-16f);
    float4 b0 = *(const float4*)(bias + lane * 8 + 0);
    float4 b1 = *(const float4*)(bias + lane * 8 + 4);
    float4 o0 = make_float4(acc[0]*inv + b0.x, acc[1]*inv + b0.y,
                            acc[2]*inv + b0.z, acc[3]*inv + b0.w);
    float4 o1 = make_float4(acc[4]*inv + b1.x, acc[5]*inv + b1.y,
                            acc[6]*inv + b1.z, acc[7]*inv + b1.w);
    *(float4*)(out + base + 0) = o0;
    *(float4*)(out + base + 4) = o1;
}

// ---------------------------------------------------------------------------
extern "C" void kernel_launch(void* const* d_in, const int* in_sizes, int n_in,
                              void* d_out, int out_size)
{
    const float* x       = (const float*)d_in[0];
    const int*   ei      = (const int*)d_in[1];     // int32 edge index [2, E]
    const float* W       = (const float*)d_in[2];
    const float* att_src = (const float*)d_in[3];
    const float* att_dst = (const float*)d_in[4];
    const float* bias    = (const float*)d_in[5];
    float*       out     = (float*)d_out;

    int n = in_sizes[0] / 256;      // 50000
    int E = in_sizes[1] / 2;        // 800000
    int nb = (n + 1023) / 1024;
    int nx8 = n * 256 / 8;
    int nw8 = 256 * 256 / 8;

    // One-time setup on the first (uncaptured correctness) call.
    static int inited = 0;
    static cudaStream_t s_side = 0;
    static cudaEvent_t ev_fork = 0, ev_join = 0;
    static int use_side = 0;
    if (!inited) {
        cudaFuncSetAttribute(gemm_bf16x3_kernel,
                             cudaFuncAttributeMaxDynamicSharedMemorySize,
                             SMEM_TOT);
        if (cudaStreamCreateWithFlags(&s_side, cudaStreamNonBlocking)
                == cudaSuccess &&
            cudaEventCreateWithFlags(&ev_fork, cudaEventDisableTiming)
                == cudaSuccess &&
            cudaEventCreateWithFlags(&ev_join, cudaEventDisableTiming)
                == cudaSuccess)
            use_side = 1;
        inited = 1;
    }
    cudaStream_t sc = use_side ? s_side : (cudaStream_t)0;

    // Main stream: zero -> convert -> gemm. Side stream (forked after zero):
    // hist -> scan1..3 -> scatter. Join before agg.
    zero_kernel<<<(n * HEADS + 255) / 256, 256>>>(n);
    if (use_side) {
        cudaEventRecord(ev_fork, 0);
        cudaStreamWaitEvent(s_side, ev_fork, 0);
    }
    convert_kernel<<<(nx8 + nw8 + 255) / 256, 256>>>(x, W, nx8, nw8);
    hist_kernel<<<(E + 255) / 256, 256, 0, sc>>>(ei, E);

    dim3 ggrid(1, (n + BM - 1) / BM);
    gemm_bf16x3_kernel<<<ggrid, 512, SMEM_TOT>>>(att_src, att_dst, n);

    scan1_kernel<<<nb, 1024, 0, sc>>>(n);
    scan2_kernel<<<1, 64, 0, sc>>>(nb, n);
    scan3_kernel<<<nb, 1024, 0, sc>>>(n);
    scatter_kernel<<<(E + 255) / 256, 256, 0, sc>>>(ei, E);

    if (use_side) {
        cudaEventRecord(ev_join, s_side);
        cudaStreamWaitEvent(0, ev_join, 0);
    }
    agg_kernel<<<(n * 32 + 255) / 256, 256>>>(bias, out, n);
}